// round 15
// baseline (speedup 1.0000x reference)
#include <cuda_runtime.h>
#include <cuda_fp16.h>
#include <math.h>
#include <stdint.h>

#define SEQ   2048
#define DM    2048
#define NH    32
#define NG    8
#define HD    64
#define BATCH 2
#define NTOK  (BATCH*SEQ)   // 4096
#define FTOT  3072          // 2048 q + 512 k + 512 v

// fold softmax scale and log2(e) into Q (scores land in log2 domain)
#define QSC   (0.125f * 1.44269504088896340736f)

// ---------------- scratch (static device globals; no allocation) ----------------
__device__ float  g_P  [(size_t)NTOK*FTOT];
__device__ __half g_Qh [(size_t)BATCH*NH*SEQ*HD];
__device__ __half g_Kh [(size_t)BATCH*NG*SEQ*HD];
__device__ __half g_Vh [(size_t)BATCH*NG*SEQ*HD];
__device__ __half g_AOh[(size_t)NTOK*DM];
__device__ float  g_cos[SEQ*32];
__device__ float  g_sin[SEQ*32];

__device__ __half g_xh [(size_t)NTOK*DM];
__device__ __half g_Wqh[(size_t)DM *DM];
__device__ __half g_Wkh[(size_t)512*DM];
__device__ __half g_Wvh[(size_t)512*DM];
__device__ __half g_Woh[(size_t)DM *DM];

// ===================== helpers =====================
__device__ __forceinline__ uint32_t smem_u32(const void* p) {
    uint32_t a;
    asm("{ .reg .u64 t; cvta.to.shared.u64 t, %1; cvt.u32.u64 %0, t; }" : "=r"(a) : "l"(p));
    return a;
}
__device__ __forceinline__ void cp_async16(uint32_t dst, const void* src) {
    asm volatile("cp.async.cg.shared.global [%0], [%1], 16;" :: "r"(dst), "l"(src) : "memory");
}
#define CP_COMMIT() asm volatile("cp.async.commit_group;" ::: "memory")
#define CP_WAIT(n)  asm volatile("cp.async.wait_group %0;" :: "n"(n) : "memory")

__device__ __forceinline__ void ldsm4(uint32_t* r, uint32_t addr) {
    asm volatile("ldmatrix.sync.aligned.m8n8.x4.shared.b16 {%0,%1,%2,%3}, [%4];"
                 : "=r"(r[0]), "=r"(r[1]), "=r"(r[2]), "=r"(r[3]) : "r"(addr));
}
__device__ __forceinline__ void ldsm4t(uint32_t* r, uint32_t addr) {
    asm volatile("ldmatrix.sync.aligned.m8n8.x4.trans.shared.b16 {%0,%1,%2,%3}, [%4];"
                 : "=r"(r[0]), "=r"(r[1]), "=r"(r[2]), "=r"(r[3]) : "r"(addr));
}
__device__ __forceinline__ void mma16816h(float* d, const uint32_t* a, const uint32_t* b) {
    asm volatile("mma.sync.aligned.m16n8k16.row.col.f32.f16.f16.f32 "
                 "{%0,%1,%2,%3}, {%4,%5,%6,%7}, {%8,%9}, {%0,%1,%2,%3};"
                 : "+f"(d[0]), "+f"(d[1]), "+f"(d[2]), "+f"(d[3])
                 : "r"(a[0]), "r"(a[1]), "r"(a[2]), "r"(a[3]), "r"(b[0]), "r"(b[1]));
}
__device__ __forceinline__ uint32_t pack_f16x2(float lo, float hi) {
    uint32_t r;
    asm("cvt.rn.f16x2.f32 %0, %1, %2;" : "=r"(r) : "f"(hi), "f"(lo));
    return r;
}

// GEMM smem tile: rows x 32 halves (64B/row), swizzle: chunk' = chunk ^ ((row>>1)&3)
__device__ __forceinline__ uint32_t swz32(int row, int chunk) {
    return (uint32_t)(row*64 + ((chunk ^ ((row >> 1) & 3)) * 16));
}
// attention smem tile: rows of 64 halves (128B), swizzle: ch' = ch ^ (row&7)
__device__ __forceinline__ uint32_t hswz(int row, int ch) {
    return (uint32_t)(row*128 + ((ch ^ (row & 7)) * 16));
}

// ===================== fp32 -> fp16 conversion =====================
__global__ void tohalf_kernel(const float* __restrict__ src, uint32_t* __restrict__ dst, int npairs)
{
    int i = blockIdx.x*256 + threadIdx.x;
    if (i >= npairs) return;
    float2 v = ((const float2*)src)[i];
    dst[i] = pack_f16x2(v.x, v.y);
}

// ===================== shared GEMM body =====================
__device__ __forceinline__ void gemm_body(const __half* __restrict__ Ap0,
                                          const __half* __restrict__ Bp0,
                                          const float* __restrict__ biasl,
                                          float* __restrict__ Cb,
                                          int Kp, int ldc)
{
    __shared__ __half As[2][128*32];
    __shared__ __half Bs[2][128*32];

    const int tid  = threadIdx.x;
    const int lane = tid & 31;
    const int wid  = tid >> 5;
    const int wm   = wid >> 2;
    const int wn   = wid & 3;

    const uint32_t asb[2] = { smem_u32(As[0]), smem_u32(As[1]) };
    const uint32_t bsb[2] = { smem_u32(Bs[0]), smem_u32(Bs[1]) };

    const int lrow = tid >> 2;
    const int lc   = tid & 3;

    float acc[4][4][4];
#pragma unroll
    for (int i = 0; i < 4; i++)
#pragma unroll
        for (int j = 0; j < 4; j++)
#pragma unroll
            for (int e = 0; e < 4; e++) acc[i][j][e] = 0.f;

    const int nk = Kp / 32;

    {
#pragma unroll
        for (int h = 0; h < 2; h++) {
            int row = lrow + h*64;
            cp_async16(asb[0] + swz32(row, lc), Ap0 + (size_t)row*Kp + lc*8);
            cp_async16(bsb[0] + swz32(row, lc), Bp0 + (size_t)row*Kp + lc*8);
        }
        CP_COMMIT();
    }

    for (int t = 0; t < nk; t++) {
        const int st = t & 1;
        if (t + 1 < nk) {
            const __half* Ap = Ap0 + (t+1)*32;
            const __half* Bp = Bp0 + (t+1)*32;
#pragma unroll
            for (int h = 0; h < 2; h++) {
                int row = lrow + h*64;
                cp_async16(asb[st^1] + swz32(row, lc), Ap + (size_t)row*Kp + lc*8);
                cp_async16(bsb[st^1] + swz32(row, lc), Bp + (size_t)row*Kp + lc*8);
            }
            CP_COMMIT();
            CP_WAIT(1);
        } else {
            CP_WAIT(0);
        }
        __syncthreads();

#pragma unroll
        for (int ks = 0; ks < 2; ks++) {
            uint32_t afr[4][4];
#pragma unroll
            for (int mf = 0; mf < 4; mf++) {
                int row = wm*64 + mf*16 + (lane & 15);
                int ch  = ks*2 + (lane >> 4);
                ldsm4(afr[mf], asb[st] + swz32(row, ch));
            }
            uint32_t bfr[2][4];
#pragma unroll
            for (int nb = 0; nb < 2; nb++) {
                int row = wn*32 + nb*16 + ((lane >> 4) << 3) + (lane & 7);
                int ch  = ks*2 + ((lane >> 3) & 1);
                ldsm4(bfr[nb], bsb[st] + swz32(row, ch));
            }
#pragma unroll
            for (int mf = 0; mf < 4; mf++) {
#pragma unroll
                for (int nb = 0; nb < 2; nb++) {
                    mma16816h(acc[mf][2*nb+0], afr[mf], &bfr[nb][0]);
                    mma16816h(acc[mf][2*nb+1], afr[mf], &bfr[nb][2]);
                }
            }
        }
        __syncthreads();
    }

#pragma unroll
    for (int mf = 0; mf < 4; mf++) {
        int ml = wm*64 + mf*16 + (lane >> 2);
#pragma unroll
        for (int nf = 0; nf < 4; nf++) {
            int nl = wn*32 + nf*8 + 2*(lane & 3);
            float b0 = biasl[nl], b1 = biasl[nl+1];
            float2 v0 = make_float2(acc[mf][nf][0] + b0, acc[mf][nf][1] + b1);
            float2 v1 = make_float2(acc[mf][nf][2] + b0, acc[mf][nf][3] + b1);
            *(float2*)(Cb + (size_t)ml*ldc + nl)     = v0;
            *(float2*)(Cb + (size_t)(ml+8)*ldc + nl) = v1;
        }
    }
}

// fused QKV: grid (24, 32); cols [0:2048)=Wq, [2048:2560)=Wk, [2560:3072)=Wv
__global__ __launch_bounds__(256, 2)
void qkv_gemm_kernel(const __half* __restrict__ xh,
                     const __half* __restrict__ Wq, const __half* __restrict__ Wk,
                     const __half* __restrict__ Wv,
                     const float* __restrict__ bq, const float* __restrict__ bk,
                     const float* __restrict__ bv,
                     float* __restrict__ P)
{
    const int bn = blockIdx.x * 128;
    const int bm = blockIdx.y * 128;
    const __half* W; const float* bias; int ln;
    if (bn < 2048)      { W = Wq; bias = bq; ln = bn; }
    else if (bn < 2560) { W = Wk; bias = bk; ln = bn - 2048; }
    else                { W = Wv; bias = bv; ln = bn - 2560; }
    gemm_body(xh + (size_t)bm*DM, W + (size_t)ln*DM, bias + ln,
              P + (size_t)bm*FTOT + bn, DM, FTOT);
}

__global__ __launch_bounds__(256, 2)
void gemm_mma_kernel(const __half* __restrict__ A, const __half* __restrict__ B,
                     const float* __restrict__ bias, float* __restrict__ C,
                     int Kp, int ldc)
{
    const int bn = blockIdx.x * 128;
    const int bm = blockIdx.y * 128;
    gemm_body(A + (size_t)bm*Kp, B + (size_t)bn*Kp, bias + bn,
              C + (size_t)bm*ldc + bn, Kp, ldc);
}

// ===================== RoPE table =====================
__global__ void rope_table_kernel() {
    __shared__ double th[32];
    int tid = threadIdx.x;
    if (tid < 32) th[tid] = pow(10000.0, -(double)tid / 32.0);
    __syncthreads();
    int j = tid & 31;
    int pos = blockIdx.x*8 + (tid >> 5);
    double d = (double)pos * th[j];
    const double TWO_PI = 6.283185307179586476925286766559;
    double r = d - floor(d * (1.0/TWO_PI)) * TWO_PI;
    float c, s;
    sincosf((float)r, &s, &c);
    g_cos[(pos<<5) + j] = c;
    g_sin[(pos<<5) + j] = s;
}

// ===================== rope + scatter (paired reads) =====================
__global__ void rope_scatter_kernel() {
    int t = blockIdx.y;
    int w = blockIdx.x*256 + threadIdx.x;
    int b = t >> 11;
    int s = t & (SEQ-1);
    if (w < 1280) {
        int hh = w >> 5;
        int j  = w & 31;
        size_t pb = (size_t)t*FTOT + hh*64 + j;
        float v0 = g_P[pb];
        float v1 = g_P[pb + 32];
        float c  = g_cos[(s<<5) + j];
        float sn = g_sin[(s<<5) + j];
        float o0 = fmaf(-v1, sn, v0*c);
        float o1 = fmaf( v0, sn, v1*c);
        if (hh < 32) {
            size_t base = (((size_t)(b*NH + hh))*SEQ + s)*HD + j;
            g_Qh[base]      = __float2half_rn(o0 * QSC);
            g_Qh[base + 32] = __float2half_rn(o1 * QSC);
        } else {
            int g = hh - 32;
            size_t base = (((size_t)(b*NG + g))*SEQ + s)*HD + j;
            g_Kh[base]      = __float2half_rn(o0);
            g_Kh[base + 32] = __float2half_rn(o1);
        }
    } else {
        int r = w - 1280;
        int g = r >> 6, d = r & 63;
        float v = g_P[(size_t)t*FTOT + 2560 + r];
        g_Vh[(((size_t)(b*NG + g))*SEQ + s)*HD + d] = __float2half_rn(v);
    }
}

// ===================== fp16 HMMA flash attention, BK=128 =====================
// BQ=64 (4 warps x 16 rows), K-tiles of 128 (one softmax per 128 keys),
// double-buffered K/V in dynamic smem (72KB), heavy-qt-first remap.
// grid: (SEQ/64 = 32, BATCH*NH = 64)
#define ATT_SMEM (8192 + 4*16384)   // Qs(8K) + Ks[2](16K ea) + Vs[2](16K ea) = 72KB
__global__ __launch_bounds__(128, 3)
void attn_mma_kernel()
{
    extern __shared__ __half dsm[];
    const uint32_t qsb = smem_u32(dsm);                      // 64 x 64 halves
    const uint32_t ksb[2] = { qsb + 8192,  qsb + 8192 + 16384 };   // 128 x 64 halves each
    const uint32_t vsb[2] = { qsb + 40960, qsb + 40960 + 16384 };

    const int tid = threadIdx.x, lane = tid & 31, wid = tid >> 5;
    const int qt = (int)(gridDim.x - 1 - blockIdx.x);        // heavy CTAs first
    const int bh = blockIdx.y;
    const int b = bh >> 5, h = bh & 31, g = h >> 2;

    const __half* Qp = g_Qh + ((size_t)bh*SEQ + qt*64)*HD;
    const __half* Kp = g_Kh + ((size_t)(b*NG + g))*SEQ*HD;
    const __half* Vp = g_Vh + ((size_t)(b*NG + g))*SEQ*HD;

    // prefetch Q (64 rows) + K/V tile 0 (128 rows each)
    {
        int r = tid >> 1, cb = (tid & 1) * 4;
#pragma unroll
        for (int c = 0; c < 4; c++)
            cp_async16(qsb + hswz(r, cb + c), Qp + r*64 + (cb + c)*8);
#pragma unroll
        for (int c = 0; c < 8; c++) {
            cp_async16(ksb[0] + hswz(tid, c), Kp + (size_t)tid*64 + c*8);
            cp_async16(vsb[0] + hswz(tid, c), Vp + (size_t)tid*64 + c*8);
        }
        CP_COMMIT();
    }

    float o[8][4];
    float m[2] = {-1e30f, -1e30f}, l[2] = {0.f, 0.f};
#pragma unroll
    for (int f = 0; f < 8; f++)
#pragma unroll
        for (int e = 0; e < 4; e++) o[f][e] = 0.f;

    uint32_t qf[4][4];
    const int nkt = (qt + 2) >> 1;        // number of 128-wide K tiles

    for (int kt = 0; kt < nkt; kt++) {
        const int st = kt & 1;
        if (kt + 1 < nkt) {
            const __half* Kn = Kp + (size_t)(kt + 1)*128*64;
            const __half* Vn = Vp + (size_t)(kt + 1)*128*64;
#pragma unroll
            for (int c = 0; c < 8; c++) {
                cp_async16(ksb[st^1] + hswz(tid, c), Kn + (size_t)tid*64 + c*8);
                cp_async16(vsb[st^1] + hswz(tid, c), Vn + (size_t)tid*64 + c*8);
            }
            CP_COMMIT();
            CP_WAIT(1);
        } else {
            CP_WAIT(0);
        }
        __syncthreads();

        if (kt == 0) {
#pragma unroll
            for (int kk = 0; kk < 4; kk++)
                ldsm4(qf[kk], qsb + hswz(wid*16 + (lane & 15), kk*2 + (lane >> 4)));
        }

        // S = Q K^T over 128 keys (log2 units; scale folded into Q)
        float s[16][4];
#pragma unroll
        for (int f = 0; f < 16; f++)
#pragma unroll
            for (int e = 0; e < 4; e++) s[f][e] = 0.f;

#pragma unroll
        for (int kk = 0; kk < 4; kk++) {
#pragma unroll
            for (int tb2 = 0; tb2 < 8; tb2++) {
                uint32_t kb[4];
                ldsm4(kb, ksb[st] + hswz((tb2*2 + ((lane >> 4) & 1))*8 + (lane & 7),
                                         kk*2 + ((lane >> 3) & 1)));
                mma16816h(s[tb2*2 + 0], qf[kk], &kb[0]);
                mma16816h(s[tb2*2 + 1], qf[kk], &kb[2]);
            }
        }

        // causal mask (last tile only)
        if (kt == nkt - 1) {
            int r0 = qt*64 + wid*16 + (lane >> 2);
#pragma unroll
            for (int f = 0; f < 16; f++) {
                int c0 = kt*128 + f*8 + (lane & 3)*2;
#pragma unroll
                for (int e = 0; e < 4; e++) {
                    int row = r0 + ((e >> 1) << 3);
                    int col = c0 + (e & 1);
                    if (col > row) s[f][e] = -1e30f;
                }
            }
        }

        // online softmax (base 2), one pass per 128 keys
        float fsc[2];
#pragma unroll
        for (int rh = 0; rh < 2; rh++) {
            float mx = m[rh];
#pragma unroll
            for (int f = 0; f < 16; f++)
                mx = fmaxf(mx, fmaxf(s[f][2*rh], s[f][2*rh + 1]));
            mx = fmaxf(mx, __shfl_xor_sync(0xffffffffu, mx, 1));
            mx = fmaxf(mx, __shfl_xor_sync(0xffffffffu, mx, 2));
            fsc[rh] = exp2f(m[rh] - mx);
            float rs = 0.f;
#pragma unroll
            for (int f = 0; f < 16; f++) {
                s[f][2*rh]     = exp2f(s[f][2*rh]     - mx);
                s[f][2*rh + 1] = exp2f(s[f][2*rh + 1] - mx);
                rs += s[f][2*rh] + s[f][2*rh + 1];
            }
            rs += __shfl_xor_sync(0xffffffffu, rs, 1);
            rs += __shfl_xor_sync(0xffffffffu, rs, 2);
            l[rh] = l[rh]*fsc[rh] + rs;
            m[rh] = mx;
        }
#pragma unroll
        for (int f = 0; f < 8; f++) {
            o[f][0] *= fsc[0]; o[f][1] *= fsc[0];
            o[f][2] *= fsc[1]; o[f][3] *= fsc[1];
        }

        // O += P V   (V tile: 128 rows x 64 cols; kk over 8 K-chunks of 16)
#pragma unroll
        for (int kk = 0; kk < 8; kk++) {
            uint32_t pa[4];
            pa[0] = pack_f16x2(s[2*kk][0],   s[2*kk][1]);
            pa[1] = pack_f16x2(s[2*kk][2],   s[2*kk][3]);
            pa[2] = pack_f16x2(s[2*kk+1][0], s[2*kk+1][1]);
            pa[3] = pack_f16x2(s[2*kk+1][2], s[2*kk+1][3]);
#pragma unroll
            for (int db2 = 0; db2 < 4; db2++) {
                uint32_t vb[4];
                ldsm4t(vb, vsb[st] + hswz(kk*16 + ((lane >> 3) & 1)*8 + (lane & 7),
                                          db2*2 + ((lane >> 4) & 1)));
                mma16816h(o[db2*2 + 0], pa, &vb[0]);
                mma16816h(o[db2*2 + 1], pa, &vb[2]);
            }
        }
        __syncthreads();
    }

    // epilogue: normalize, write fp16
    float inv0 = 1.f / l[0], inv1 = 1.f / l[1];
    int r0 = qt*64 + wid*16 + (lane >> 2);
    int t0 = b*SEQ + r0;
    uint32_t* AO32 = (uint32_t*)g_AOh;
#pragma unroll
    for (int f = 0; f < 8; f++) {
        int d = h*64 + f*8 + (lane & 3)*2;
        AO32[((size_t)t0*DM + d) >> 1]     = pack_f16x2(o[f][0]*inv0, o[f][1]*inv0);
        AO32[((size_t)(t0+8)*DM + d) >> 1] = pack_f16x2(o[f][2]*inv1, o[f][3]*inv1);
    }
}

// ===================== launch =====================
extern "C" void kernel_launch(void* const* d_in, const int* in_sizes, int n_in,
                              void* d_out, int out_size)
{
    const float* x  = (const float*)d_in[0];
    const float* Wq = (const float*)d_in[1];
    const float* bq = (const float*)d_in[2];
    const float* Wk = (const float*)d_in[3];
    const float* bk = (const float*)d_in[4];
    const float* Wv = (const float*)d_in[5];
    const float* bv = (const float*)d_in[6];
    const float* Wo = (const float*)d_in[7];
    const float* bo = (const float*)d_in[8];
    float* out = (float*)d_out;

    cudaFuncSetAttribute(attn_mma_kernel, cudaFuncAttributeMaxDynamicSharedMemorySize, ATT_SMEM);

    float *pP = nullptr;
    __half *pxh, *pWqh, *pWkh, *pWvh, *pWoh, *pAOh;
    cudaGetSymbolAddress((void**)&pP,   g_P);
    cudaGetSymbolAddress((void**)&pxh,  g_xh);
    cudaGetSymbolAddress((void**)&pWqh, g_Wqh);
    cudaGetSymbolAddress((void**)&pWkh, g_Wkh);
    cudaGetSymbolAddress((void**)&pWvh, g_Wvh);
    cudaGetSymbolAddress((void**)&pWoh, g_Woh);
    cudaGetSymbolAddress((void**)&pAOh, g_AOh);

    // fp32 -> fp16 conversions
    tohalf_kernel<<<(NTOK*DM/2)/256, 256>>>(x,  (uint32_t*)pxh,  NTOK*DM/2);
    tohalf_kernel<<<(DM*DM/2)/256,   256>>>(Wq, (uint32_t*)pWqh, DM*DM/2);
    tohalf_kernel<<<(512*DM/2)/256,  256>>>(Wk, (uint32_t*)pWkh, 512*DM/2);
    tohalf_kernel<<<(512*DM/2)/256,  256>>>(Wv, (uint32_t*)pWvh, 512*DM/2);
    tohalf_kernel<<<(DM*DM/2)/256,   256>>>(Wo, (uint32_t*)pWoh, DM*DM/2);

    // fused QKV projection
    qkv_gemm_kernel<<<dim3(FTOT/128, NTOK/128), 256>>>(pxh, pWqh, pWkh, pWvh, bq, bk, bv, pP);

    rope_table_kernel<<<SEQ/8, 256>>>();
    rope_scatter_kernel<<<dim3(7, NTOK), 256>>>();

    attn_mma_kernel<<<dim3(SEQ/64, BATCH*NH), 128, ATT_SMEM>>>();

    // output projection
    gemm_mma_kernel<<<dim3(DM/128, NTOK/128), 256>>>(pAOh, pWoh, bo, out, DM, DM);
}

// round 16
// speedup vs baseline: 1.1499x; 1.1499x over previous
#include <cuda_runtime.h>
#include <cuda_fp16.h>
#include <math.h>
#include <stdint.h>

#define SEQ   2048
#define DM    2048
#define NH    32
#define NG    8
#define HD    64
#define BATCH 2
#define NTOK  (BATCH*SEQ)   // 4096
#define FTOT  3072          // 2048 q + 512 k + 512 v

// fold softmax scale and log2(e) into Q (scores land in log2 domain)
#define QSC   (0.125f * 1.44269504088896340736f)

// ---------------- scratch (static device globals; no allocation) ----------------
__device__ __half g_Ph [(size_t)NTOK*FTOT];   // qkv projection output (fp16)
__device__ __half g_Qh [(size_t)BATCH*NH*SEQ*HD];
__device__ __half g_Kh [(size_t)BATCH*NG*SEQ*HD];
__device__ __half g_Vh [(size_t)BATCH*NG*SEQ*HD];
__device__ __half g_AOh[(size_t)NTOK*DM];
__device__ float  g_cos[SEQ*32];
__device__ float  g_sin[SEQ*32];

__device__ __half g_xh [(size_t)NTOK*DM];
__device__ __half g_Wqh[(size_t)DM *DM];
__device__ __half g_Wkh[(size_t)512*DM];
__device__ __half g_Wvh[(size_t)512*DM];
__device__ __half g_Woh[(size_t)DM *DM];

// ===================== helpers =====================
__device__ __forceinline__ uint32_t smem_u32(const void* p) {
    uint32_t a;
    asm("{ .reg .u64 t; cvta.to.shared.u64 t, %1; cvt.u32.u64 %0, t; }" : "=r"(a) : "l"(p));
    return a;
}
__device__ __forceinline__ void cp_async16(uint32_t dst, const void* src) {
    asm volatile("cp.async.cg.shared.global [%0], [%1], 16;" :: "r"(dst), "l"(src) : "memory");
}
#define CP_COMMIT() asm volatile("cp.async.commit_group;" ::: "memory")
#define CP_WAIT(n)  asm volatile("cp.async.wait_group %0;" :: "n"(n) : "memory")

__device__ __forceinline__ void ldsm4(uint32_t* r, uint32_t addr) {
    asm volatile("ldmatrix.sync.aligned.m8n8.x4.shared.b16 {%0,%1,%2,%3}, [%4];"
                 : "=r"(r[0]), "=r"(r[1]), "=r"(r[2]), "=r"(r[3]) : "r"(addr));
}
__device__ __forceinline__ void ldsm4t(uint32_t* r, uint32_t addr) {
    asm volatile("ldmatrix.sync.aligned.m8n8.x4.trans.shared.b16 {%0,%1,%2,%3}, [%4];"
                 : "=r"(r[0]), "=r"(r[1]), "=r"(r[2]), "=r"(r[3]) : "r"(addr));
}
__device__ __forceinline__ void mma16816h(float* d, const uint32_t* a, const uint32_t* b) {
    asm volatile("mma.sync.aligned.m16n8k16.row.col.f32.f16.f16.f32 "
                 "{%0,%1,%2,%3}, {%4,%5,%6,%7}, {%8,%9}, {%0,%1,%2,%3};"
                 : "+f"(d[0]), "+f"(d[1]), "+f"(d[2]), "+f"(d[3])
                 : "r"(a[0]), "r"(a[1]), "r"(a[2]), "r"(a[3]), "r"(b[0]), "r"(b[1]));
}
__device__ __forceinline__ uint32_t pack_f16x2(float lo, float hi) {
    uint32_t r;
    asm("cvt.rn.f16x2.f32 %0, %1, %2;" : "=r"(r) : "f"(hi), "f"(lo));
    return r;
}

// GEMM smem tile: rows x 32 halves (64B/row), swizzle: chunk' = chunk ^ ((row>>1)&3)
__device__ __forceinline__ uint32_t swz32(int row, int chunk) {
    return (uint32_t)(row*64 + ((chunk ^ ((row >> 1) & 3)) * 16));
}
// attention smem tile: rows of 64 halves (128B), swizzle: ch' = ch ^ (row&7)
__device__ __forceinline__ uint32_t hswz(int row, int ch) {
    return (uint32_t)(row*128 + ((ch ^ (row & 7)) * 16));
}

// ===================== merged fp32 -> fp16 conversion (one launch) =====================
// blocks: x 16384 | Wq 8192 | Wk 2048 | Wv 2048 | Wo 8192  = 36864
__global__ void tohalf_all_kernel(const float* __restrict__ x,  const float* __restrict__ Wq,
                                  const float* __restrict__ Wk, const float* __restrict__ Wv,
                                  const float* __restrict__ Wo,
                                  uint32_t* __restrict__ xh,  uint32_t* __restrict__ wqh,
                                  uint32_t* __restrict__ wkh, uint32_t* __restrict__ wvh,
                                  uint32_t* __restrict__ woh)
{
    int bidx = blockIdx.x;
    const float* src; uint32_t* dst; int base;
    if (bidx < 16384)      { src = x;  dst = xh;  base = bidx; }
    else if (bidx < 24576) { src = Wq; dst = wqh; base = bidx - 16384; }
    else if (bidx < 26624) { src = Wk; dst = wkh; base = bidx - 24576; }
    else if (bidx < 28672) { src = Wv; dst = wvh; base = bidx - 26624; }
    else                   { src = Wo; dst = woh; base = bidx - 28672; }
    int i = base*256 + threadIdx.x;
    float2 v = ((const float2*)src)[i];
    dst[i] = pack_f16x2(v.x, v.y);
}

// ===================== shared GEMM body (templated output type) =====================
template<bool HOUT>
__device__ __forceinline__ void gemm_body(const __half* __restrict__ Ap0,
                                          const __half* __restrict__ Bp0,
                                          const float* __restrict__ biasl,
                                          void* __restrict__ Cb,
                                          int Kp, int ldc)
{
    __shared__ __half As[2][128*32];
    __shared__ __half Bs[2][128*32];

    const int tid  = threadIdx.x;
    const int lane = tid & 31;
    const int wid  = tid >> 5;
    const int wm   = wid >> 2;
    const int wn   = wid & 3;

    const uint32_t asb[2] = { smem_u32(As[0]), smem_u32(As[1]) };
    const uint32_t bsb[2] = { smem_u32(Bs[0]), smem_u32(Bs[1]) };

    const int lrow = tid >> 2;
    const int lc   = tid & 3;

    float acc[4][4][4];
#pragma unroll
    for (int i = 0; i < 4; i++)
#pragma unroll
        for (int j = 0; j < 4; j++)
#pragma unroll
            for (int e = 0; e < 4; e++) acc[i][j][e] = 0.f;

    const int nk = Kp / 32;

    {
#pragma unroll
        for (int h = 0; h < 2; h++) {
            int row = lrow + h*64;
            cp_async16(asb[0] + swz32(row, lc), Ap0 + (size_t)row*Kp + lc*8);
            cp_async16(bsb[0] + swz32(row, lc), Bp0 + (size_t)row*Kp + lc*8);
        }
        CP_COMMIT();
    }

    for (int t = 0; t < nk; t++) {
        const int st = t & 1;
        if (t + 1 < nk) {
            const __half* Ap = Ap0 + (t+1)*32;
            const __half* Bp = Bp0 + (t+1)*32;
#pragma unroll
            for (int h = 0; h < 2; h++) {
                int row = lrow + h*64;
                cp_async16(asb[st^1] + swz32(row, lc), Ap + (size_t)row*Kp + lc*8);
                cp_async16(bsb[st^1] + swz32(row, lc), Bp + (size_t)row*Kp + lc*8);
            }
            CP_COMMIT();
            CP_WAIT(1);
        } else {
            CP_WAIT(0);
        }
        __syncthreads();

#pragma unroll
        for (int ks = 0; ks < 2; ks++) {
            uint32_t afr[4][4];
#pragma unroll
            for (int mf = 0; mf < 4; mf++) {
                int row = wm*64 + mf*16 + (lane & 15);
                int ch  = ks*2 + (lane >> 4);
                ldsm4(afr[mf], asb[st] + swz32(row, ch));
            }
            uint32_t bfr[2][4];
#pragma unroll
            for (int nb = 0; nb < 2; nb++) {
                int row = wn*32 + nb*16 + ((lane >> 4) << 3) + (lane & 7);
                int ch  = ks*2 + ((lane >> 3) & 1);
                ldsm4(bfr[nb], bsb[st] + swz32(row, ch));
            }
#pragma unroll
            for (int mf = 0; mf < 4; mf++) {
#pragma unroll
                for (int nb = 0; nb < 2; nb++) {
                    mma16816h(acc[mf][2*nb+0], afr[mf], &bfr[nb][0]);
                    mma16816h(acc[mf][2*nb+1], afr[mf], &bfr[nb][2]);
                }
            }
        }
        __syncthreads();
    }

#pragma unroll
    for (int mf = 0; mf < 4; mf++) {
        int ml = wm*64 + mf*16 + (lane >> 2);
#pragma unroll
        for (int nf = 0; nf < 4; nf++) {
            int nl = wn*32 + nf*8 + 2*(lane & 3);
            float b0 = biasl[nl], b1 = biasl[nl+1];
            if (HOUT) {
                __half* C = (__half*)Cb;
                *(uint32_t*)(C + (size_t)ml*ldc + nl)     = pack_f16x2(acc[mf][nf][0] + b0, acc[mf][nf][1] + b1);
                *(uint32_t*)(C + (size_t)(ml+8)*ldc + nl) = pack_f16x2(acc[mf][nf][2] + b0, acc[mf][nf][3] + b1);
            } else {
                float* C = (float*)Cb;
                float2 v0 = make_float2(acc[mf][nf][0] + b0, acc[mf][nf][1] + b1);
                float2 v1 = make_float2(acc[mf][nf][2] + b0, acc[mf][nf][3] + b1);
                *(float2*)(C + (size_t)ml*ldc + nl)     = v0;
                *(float2*)(C + (size_t)(ml+8)*ldc + nl) = v1;
            }
        }
    }
}

// fused QKV: grid (24, 32); cols [0:2048)=Wq, [2048:2560)=Wk, [2560:3072)=Wv  (fp16 out)
__global__ __launch_bounds__(256, 2)
void qkv_gemm_kernel(const __half* __restrict__ xh,
                     const __half* __restrict__ Wq, const __half* __restrict__ Wk,
                     const __half* __restrict__ Wv,
                     const float* __restrict__ bq, const float* __restrict__ bk,
                     const float* __restrict__ bv,
                     __half* __restrict__ P)
{
    const int bn = blockIdx.x * 128;
    const int bm = blockIdx.y * 128;
    const __half* W; const float* bias; int ln;
    if (bn < 2048)      { W = Wq; bias = bq; ln = bn; }
    else if (bn < 2560) { W = Wk; bias = bk; ln = bn - 2048; }
    else                { W = Wv; bias = bv; ln = bn - 2560; }
    gemm_body<true>(xh + (size_t)bm*DM, W + (size_t)ln*DM, bias + ln,
                    P + (size_t)bm*FTOT + bn, DM, FTOT);
}

// O projection (fp32 out)
__global__ __launch_bounds__(256, 2)
void gemm_mma_kernel(const __half* __restrict__ A, const __half* __restrict__ B,
                     const float* __restrict__ bias, float* __restrict__ C,
                     int Kp, int ldc)
{
    const int bn = blockIdx.x * 128;
    const int bm = blockIdx.y * 128;
    gemm_body<false>(A + (size_t)bm*Kp, B + (size_t)bn*Kp, bias + bn,
                     C + (size_t)bm*ldc + bn, Kp, ldc);
}

// ===================== RoPE table =====================
__global__ void rope_table_kernel() {
    __shared__ double th[32];
    int tid = threadIdx.x;
    if (tid < 32) th[tid] = pow(10000.0, -(double)tid / 32.0);
    __syncthreads();
    int j = tid & 31;
    int pos = blockIdx.x*8 + (tid >> 5);
    double d = (double)pos * th[j];
    const double TWO_PI = 6.283185307179586476925286766559;
    double r = d - floor(d * (1.0/TWO_PI)) * TWO_PI;
    float c, s;
    sincosf((float)r, &s, &c);
    g_cos[(pos<<5) + j] = c;
    g_sin[(pos<<5) + j] = s;
}

// ===================== rope + scatter (fp16 in, paired reads) =====================
__global__ void rope_scatter_kernel() {
    int t = blockIdx.y;
    int w = blockIdx.x*256 + threadIdx.x;
    int b = t >> 11;
    int s = t & (SEQ-1);
    if (w < 1280) {
        int hh = w >> 5;     // 0..39: 32 q heads then 8 k groups
        int j  = w & 31;
        size_t pb = (size_t)t*FTOT + hh*64 + j;
        float v0 = __half2float(g_Ph[pb]);
        float v1 = __half2float(g_Ph[pb + 32]);
        float c  = g_cos[(s<<5) + j];
        float sn = g_sin[(s<<5) + j];
        float o0 = fmaf(-v1, sn, v0*c);
        float o1 = fmaf( v0, sn, v1*c);
        if (hh < 32) {
            size_t base = (((size_t)(b*NH + hh))*SEQ + s)*HD + j;
            g_Qh[base]      = __float2half_rn(o0 * QSC);
            g_Qh[base + 32] = __float2half_rn(o1 * QSC);
        } else {
            int g = hh - 32;
            size_t base = (((size_t)(b*NG + g))*SEQ + s)*HD + j;
            g_Kh[base]      = __float2half_rn(o0);
            g_Kh[base + 32] = __float2half_rn(o1);
        }
    } else {
        int r = w - 1280;    // 0..511
        int g = r >> 6, d = r & 63;
        g_Vh[(((size_t)(b*NG + g))*SEQ + s)*HD + d] = g_Ph[(size_t)t*FTOT + 2560 + r];
    }
}

// ===================== fp16 HMMA flash attention (R11 shape: BK=64, static smem) =====
// BQ=64 (4 warps x 16 rows), BK=64, double-buffered K/V, 3 CTAs/SM.
// grid: (SEQ/64 = 32, BATCH*NH = 64)
__global__ __launch_bounds__(128, 3)
void attn_mma_kernel()
{
    __shared__ __half Qs[64*64];
    __shared__ __half Ks[2][64*64];
    __shared__ __half Vs[2][64*64];

    const int tid = threadIdx.x, lane = tid & 31, wid = tid >> 5;
    const int qt = blockIdx.x, bh = blockIdx.y;
    const int b = bh >> 5, h = bh & 31, g = h >> 2;

    const __half* Qp = g_Qh + ((size_t)bh*SEQ + qt*64)*HD;
    const __half* Kp = g_Kh + ((size_t)(b*NG + g))*SEQ*HD;
    const __half* Vp = g_Vh + ((size_t)(b*NG + g))*SEQ*HD;

    const uint32_t qsb = smem_u32(Qs);
    const uint32_t ksb[2] = { smem_u32(Ks[0]), smem_u32(Ks[1]) };
    const uint32_t vsb[2] = { smem_u32(Vs[0]), smem_u32(Vs[1]) };

    // load Q + prefetch K/V tile 0 (64 rows x 8 chunks each)
    {
        int r = tid >> 1, cb = (tid & 1) * 4;
#pragma unroll
        for (int c = 0; c < 4; c++) {
            cp_async16(qsb + hswz(r, cb + c), Qp + r*64 + (cb + c)*8);
            cp_async16(ksb[0] + hswz(r, cb + c), Kp + (size_t)r*64 + (cb + c)*8);
            cp_async16(vsb[0] + hswz(r, cb + c), Vp + (size_t)r*64 + (cb + c)*8);
        }
        CP_COMMIT();
    }

    float o[8][4];
    float m[2] = {-1e30f, -1e30f}, l[2] = {0.f, 0.f};
#pragma unroll
    for (int f = 0; f < 8; f++)
#pragma unroll
        for (int e = 0; e < 4; e++) o[f][e] = 0.f;

    uint32_t qf[4][4];
    const int nkt = qt + 1;

    for (int kt = 0; kt < nkt; kt++) {
        const int st = kt & 1;
        if (kt + 1 < nkt) {
            int r = tid >> 1, cb = (tid & 1) * 4;
            const __half* Kn = Kp + (size_t)(kt + 1)*64*64;
            const __half* Vn = Vp + (size_t)(kt + 1)*64*64;
#pragma unroll
            for (int c = 0; c < 4; c++) {
                cp_async16(ksb[st^1] + hswz(r, cb + c), Kn + (size_t)r*64 + (cb + c)*8);
                cp_async16(vsb[st^1] + hswz(r, cb + c), Vn + (size_t)r*64 + (cb + c)*8);
            }
            CP_COMMIT();
            CP_WAIT(1);
        } else {
            CP_WAIT(0);
        }
        __syncthreads();

        if (kt == 0) {
#pragma unroll
            for (int kk = 0; kk < 4; kk++)
                ldsm4(qf[kk], qsb + hswz(wid*16 + (lane & 15), kk*2 + (lane >> 4)));
        }

        // S = Q K^T  (log2 units; scale folded into Q)
        float s[8][4];
#pragma unroll
        for (int f = 0; f < 8; f++)
#pragma unroll
            for (int e = 0; e < 4; e++) s[f][e] = 0.f;

#pragma unroll
        for (int kk = 0; kk < 4; kk++) {
#pragma unroll
            for (int tb2 = 0; tb2 < 4; tb2++) {
                uint32_t kb[4];
                ldsm4(kb, ksb[st] + hswz((tb2*2 + ((lane >> 4) & 1))*8 + (lane & 7),
                                         kk*2 + ((lane >> 3) & 1)));
                mma16816h(s[tb2*2 + 0], qf[kk], &kb[0]);
                mma16816h(s[tb2*2 + 1], qf[kk], &kb[2]);
            }
        }

        // causal mask (diagonal tile only)
        if (kt == qt) {
            int r0 = qt*64 + wid*16 + (lane >> 2);
#pragma unroll
            for (int f = 0; f < 8; f++) {
                int c0 = kt*64 + f*8 + (lane & 3)*2;
#pragma unroll
                for (int e = 0; e < 4; e++) {
                    int row = r0 + ((e >> 1) << 3);
                    int col = c0 + (e & 1);
                    if (col > row) s[f][e] = -1e30f;
                }
            }
        }

        // online softmax (base 2)
        float fsc[2];
#pragma unroll
        for (int rh = 0; rh < 2; rh++) {
            float mx = m[rh];
#pragma unroll
            for (int f = 0; f < 8; f++)
                mx = fmaxf(mx, fmaxf(s[f][2*rh], s[f][2*rh + 1]));
            mx = fmaxf(mx, __shfl_xor_sync(0xffffffffu, mx, 1));
            mx = fmaxf(mx, __shfl_xor_sync(0xffffffffu, mx, 2));
            fsc[rh] = exp2f(m[rh] - mx);
            float rs = 0.f;
#pragma unroll
            for (int f = 0; f < 8; f++) {
                s[f][2*rh]     = exp2f(s[f][2*rh]     - mx);
                s[f][2*rh + 1] = exp2f(s[f][2*rh + 1] - mx);
                rs += s[f][2*rh] + s[f][2*rh + 1];
            }
            rs += __shfl_xor_sync(0xffffffffu, rs, 1);
            rs += __shfl_xor_sync(0xffffffffu, rs, 2);
            l[rh] = l[rh]*fsc[rh] + rs;
            m[rh] = mx;
        }
#pragma unroll
        for (int f = 0; f < 8; f++) {
            o[f][0] *= fsc[0]; o[f][1] *= fsc[0];
            o[f][2] *= fsc[1]; o[f][3] *= fsc[1];
        }

        // P -> fp16 A-frags
        uint32_t pa[4][4];
#pragma unroll
        for (int kk = 0; kk < 4; kk++) {
            pa[kk][0] = pack_f16x2(s[2*kk][0],   s[2*kk][1]);
            pa[kk][1] = pack_f16x2(s[2*kk][2],   s[2*kk][3]);
            pa[kk][2] = pack_f16x2(s[2*kk+1][0], s[2*kk+1][1]);
            pa[kk][3] = pack_f16x2(s[2*kk+1][2], s[2*kk+1][3]);
        }

        // O += P V
#pragma unroll
        for (int kk = 0; kk < 4; kk++) {
#pragma unroll
            for (int db2 = 0; db2 < 4; db2++) {
                uint32_t vb[4];
                ldsm4t(vb, vsb[st] + hswz(kk*16 + ((lane >> 3) & 1)*8 + (lane & 7),
                                          db2*2 + ((lane >> 4) & 1)));
                mma16816h(o[db2*2 + 0], pa[kk], &vb[0]);
                mma16816h(o[db2*2 + 1], pa[kk], &vb[2]);
            }
        }
        __syncthreads();
    }

    // epilogue: normalize, write fp16
    float inv0 = 1.f / l[0], inv1 = 1.f / l[1];
    int r0 = qt*64 + wid*16 + (lane >> 2);
    int t0 = b*SEQ + r0;
    uint32_t* AO32 = (uint32_t*)g_AOh;
#pragma unroll
    for (int f = 0; f < 8; f++) {
        int d = h*64 + f*8 + (lane & 3)*2;
        AO32[((size_t)t0*DM + d) >> 1]     = pack_f16x2(o[f][0]*inv0, o[f][1]*inv0);
        AO32[((size_t)(t0+8)*DM + d) >> 1] = pack_f16x2(o[f][2]*inv1, o[f][3]*inv1);
    }
}

// ===================== launch =====================
extern "C" void kernel_launch(void* const* d_in, const int* in_sizes, int n_in,
                              void* d_out, int out_size)
{
    const float* x  = (const float*)d_in[0];
    const float* Wq = (const float*)d_in[1];
    const float* bq = (const float*)d_in[2];
    const float* Wk = (const float*)d_in[3];
    const float* bk = (const float*)d_in[4];
    const float* Wv = (const float*)d_in[5];
    const float* bv = (const float*)d_in[6];
    const float* Wo = (const float*)d_in[7];
    const float* bo = (const float*)d_in[8];
    float* out = (float*)d_out;

    __half *pPh, *pxh, *pWqh, *pWkh, *pWvh, *pWoh, *pAOh;
    cudaGetSymbolAddress((void**)&pPh,  g_Ph);
    cudaGetSymbolAddress((void**)&pxh,  g_xh);
    cudaGetSymbolAddress((void**)&pWqh, g_Wqh);
    cudaGetSymbolAddress((void**)&pWkh, g_Wkh);
    cudaGetSymbolAddress((void**)&pWvh, g_Wvh);
    cudaGetSymbolAddress((void**)&pWoh, g_Woh);
    cudaGetSymbolAddress((void**)&pAOh, g_AOh);

    // all fp32 -> fp16 conversions in one launch
    tohalf_all_kernel<<<36864, 256>>>(x, Wq, Wk, Wv, Wo,
                                      (uint32_t*)pxh, (uint32_t*)pWqh, (uint32_t*)pWkh,
                                      (uint32_t*)pWvh, (uint32_t*)pWoh);

    // fused QKV projection (fp16 output)
    qkv_gemm_kernel<<<dim3(FTOT/128, NTOK/128), 256>>>(pxh, pWqh, pWkh, pWvh, bq, bk, bv, pPh);

    rope_table_kernel<<<SEQ/8, 256>>>();
    rope_scatter_kernel<<<dim3(7, NTOK), 256>>>();

    attn_mma_kernel<<<dim3(SEQ/64, BATCH*NH), 128>>>();

    // output projection (fp32 output)
    gemm_mma_kernel<<<dim3(DM/128, NTOK/128), 256>>>(pAOh, pWoh, bo, out, DM, DM);
}